// round 5
// baseline (speedup 1.0000x reference)
#include <cuda_runtime.h>
#include <cstdint>
#include <cstddef>

// ---------------------------------------------------------------------------
// DSDM classifier, fused flash-style:
//   dist[b,n] = ||x_b - A_n||,  w = exp(-dist/T),  out = (W @ M) / rowsum(W)
// Shapes: x[2048,128], A[100000,128], M[100000,100], out[2048,100], T=2.
// ---------------------------------------------------------------------------

#define CONST_B   2048
#define CONST_D   128
#define CONST_N   100000
#define CONST_C   100

#define BM        64          // batch rows per block
#define NT        64          // n (address) chunk per iteration
#define NSPLIT    4           // blocks splitting the n range
#define THREADS   256
#define CPAD      128         // M columns padded (col 100 == 1.0 -> sumexp)
#define PSTRIDE   112         // partial row stride (101 useful cols)
#define NPER      (CONST_N / NSPLIT)   // 25000, exact

// -(1 / (T * ln2)) with T = 2
#define NEG_K     (-0.72134752044448169f)

// smem layout (bytes)
#define OFF_XS2   0                       // float2[128][64]  = 65536
#define OFF_AS    65536                   // float [128][64]  = 32768
#define OFF_MS    98304                   // float [64][128]  = 32768
#define OFF_WS    131072                  // float [64][65]   = 16640
#define OFF_AN    147712                  // float [64]
#define OFF_XN    147968                  // float [64]
#define SMEM_TOTAL 148224

// scratch (allocation-free: __device__ globals)
__device__ float g_anorm[CONST_N];
__device__ float g_part[(size_t)NSPLIT * CONST_B * PSTRIDE];

// ---- packed f32x2 helpers ----
__device__ __forceinline__ void fma2(unsigned long long& d,
                                     unsigned long long a,
                                     unsigned long long b) {
    asm("fma.rn.f32x2 %0, %1, %2, %0;" : "+l"(d) : "l"(a), "l"(b));
}
__device__ __forceinline__ unsigned long long pack2(float x, float y) {
    unsigned long long r;
    asm("mov.b64 %0, {%1, %2};" : "=l"(r) : "f"(x), "f"(y));
    return r;
}
__device__ __forceinline__ void unpack2(unsigned long long v, float& a, float& b) {
    asm("mov.b64 {%0, %1}, %2;" : "=f"(a), "=f"(b) : "l"(v));
}
__device__ __forceinline__ float fsqrt_approx(float x) {
    float r; asm("sqrt.approx.f32 %0, %1;" : "=f"(r) : "f"(x)); return r;
}
__device__ __forceinline__ float fex2(float x) {
    float r; asm("ex2.approx.f32 %0, %1;" : "=f"(r) : "f"(x)); return r;
}

// ---------------------------------------------------------------------------
// Kernel 1: ||A_n||^2 per row. One warp per row, float4 loads (coalesced).
// ---------------------------------------------------------------------------
__global__ void anorm_kernel(const float* __restrict__ A) {
    int row  = blockIdx.x * 8 + (threadIdx.x >> 5);
    int lane = threadIdx.x & 31;
    if (row >= CONST_N) return;
    float4 v = *reinterpret_cast<const float4*>(A + (size_t)row * CONST_D + lane * 4);
    float s = v.x * v.x + v.y * v.y + v.z * v.z + v.w * v.w;
    #pragma unroll
    for (int o = 16; o; o >>= 1) s += __shfl_xor_sync(0xffffffffu, s, o);
    if (lane == 0) g_anorm[row] = s;
}

// ---------------------------------------------------------------------------
// Kernel 2: fused main loop. Grid (B/BM, NSPLIT), 256 threads.
// ---------------------------------------------------------------------------
__global__ void __launch_bounds__(THREADS, 1)
dsdm_main(const float* __restrict__ x,
          const float* __restrict__ A,
          const float* __restrict__ M)
{
    extern __shared__ char smem[];
    float2* xs2  = reinterpret_cast<float2*>(smem + OFF_XS2);  // [k][row] dup pairs
    float*  As   = reinterpret_cast<float*>(smem + OFF_AS);    // [k][n-local]
    float*  Ms   = reinterpret_cast<float*>(smem + OFF_MS);    // [n-local][CPAD]
    float*  Ws   = reinterpret_cast<float*>(smem + OFF_WS);    // [n-local][65] (padded)
    float*  an_s = reinterpret_cast<float*>(smem + OFF_AN);
    float*  xn_s = reinterpret_cast<float*>(smem + OFF_XN);

    const int tid  = threadIdx.x;
    const int warp = tid >> 5, lane = tid & 31;
    const int b0   = blockIdx.x * BM;
    const int nBeg = blockIdx.y * NPER;
    const int nEnd = nBeg + NPER;

    // ---- x tile: load once, compute ||x||^2, store transposed + duplicated ----
    for (int r = warp; r < BM; r += 8) {
        float4 v = *reinterpret_cast<const float4*>(x + (size_t)(b0 + r) * CONST_D + lane * 4);
        float sq = v.x * v.x + v.y * v.y + v.z * v.z + v.w * v.w;
        #pragma unroll
        for (int o = 16; o; o >>= 1) sq += __shfl_xor_sync(0xffffffffu, sq, o);
        if (lane == 0) xn_s[r] = sq;
        int k = lane * 4;
        xs2[(k + 0) * BM + r] = make_float2(v.x, v.x);
        xs2[(k + 1) * BM + r] = make_float2(v.y, v.y);
        xs2[(k + 2) * BM + r] = make_float2(v.z, v.z);
        xs2[(k + 3) * BM + r] = make_float2(v.w, v.w);
    }
    // Ms pad region: col 100 = 1.0 (so GEMM2 also produces sum(w)); 101..127 = 0
    for (int i = tid; i < NT * (CPAD - CONST_C); i += THREADS) {
        int r = i / (CPAD - CONST_C);
        int c = CONST_C + i % (CPAD - CONST_C);
        Ms[r * CPAD + c] = (c == CONST_C) ? 1.0f : 0.0f;
    }

    const int ty  = tid >> 4, tx = tid & 15;
    const int r0  = ty * 4;       // batch rows owned (both GEMMs)
    const int cg1 = tx * 4;       // GEMM1 n-local cols
    const int cg2 = tx * 8;       // GEMM2 output cols

    unsigned long long acc[4][4];
    #pragma unroll
    for (int i = 0; i < 4; i++)
        #pragma unroll
        for (int q = 0; q < 4; q++) acc[i][q] = 0ull;

    __syncthreads();

    float xn[4];
    #pragma unroll
    for (int i = 0; i < 4; i++) xn[i] = xn_s[r0 + i];

    // staging map for A-transpose: warp covers 8 rows, 4 lanes per row along k
    const int sa_i  = warp * 8 + (lane >> 2);
    const int sa_kq = lane & 3;

    for (int n0 = nBeg; n0 < nEnd; n0 += NT) {
        // ---------------- stage A (transposed k-major), M, anorm ----------------
        {
            int nIdx = n0 + sa_i;
            if (nIdx >= nEnd) nIdx = nEnd - 1;   // clamp; weights zeroed later
            const float4* arow = reinterpret_cast<const float4*>(A + (size_t)nIdx * CONST_D);
            #pragma unroll
            for (int p = 0; p < 8; p++) {
                float4 v = arow[sa_kq + 4 * p];
                int k = (sa_kq + 4 * p) * 4;
                As[(k + 0) * BM + sa_i] = v.x;
                As[(k + 1) * BM + sa_i] = v.y;
                As[(k + 2) * BM + sa_i] = v.z;
                As[(k + 3) * BM + sa_i] = v.w;
            }
        }
        for (int idx = tid; idx < NT * 25; idx += THREADS) {  // 25 float4 per M row
            int r = idx / 25, cq = idx % 25;
            int nIdx = n0 + r;
            float4 v = make_float4(0.f, 0.f, 0.f, 0.f);
            if (nIdx < nEnd)
                v = *reinterpret_cast<const float4*>(M + (size_t)nIdx * CONST_C + cq * 4);
            *reinterpret_cast<float4*>(Ms + r * CPAD + cq * 4) = v;
        }
        if (tid < NT) {
            int nIdx = n0 + tid;
            an_s[tid] = (nIdx < nEnd) ? g_anorm[nIdx] : 0.f;
        }
        __syncthreads();

        // ---------------- GEMM1: S[64 rows][64 n] = x . A^T (k = 128) ----------
        unsigned long long s2[4][2];
        #pragma unroll
        for (int i = 0; i < 4; i++) { s2[i][0] = 0ull; s2[i][1] = 0ull; }

        #pragma unroll 4
        for (int k = 0; k < CONST_D; k++) {
            double2 xa = *reinterpret_cast<const double2*>(xs2 + k * BM + r0);
            double2 xb = *reinterpret_cast<const double2*>(xs2 + k * BM + r0 + 2);
            double2 av = *reinterpret_cast<const double2*>(As + k * BM + cg1);
            unsigned long long a01 = __double_as_longlong(av.x);
            unsigned long long a23 = __double_as_longlong(av.y);
            unsigned long long x0  = __double_as_longlong(xa.x);
            unsigned long long x1  = __double_as_longlong(xa.y);
            unsigned long long x2  = __double_as_longlong(xb.x);
            unsigned long long x3  = __double_as_longlong(xb.y);
            fma2(s2[0][0], x0, a01); fma2(s2[0][1], x0, a23);
            fma2(s2[1][0], x1, a01); fma2(s2[1][1], x1, a23);
            fma2(s2[2][0], x2, a01); fma2(s2[2][1], x2, a23);
            fma2(s2[3][0], x3, a01); fma2(s2[3][1], x3, a23);
        }

        // ---------------- weights: w = exp2(-dist / (T ln2)) -------------------
        #pragma unroll
        for (int i = 0; i < 4; i++) {
            #pragma unroll
            for (int jp = 0; jp < 2; jp++) {
                float d0, d1;
                unpack2(s2[i][jp], d0, d1);
                int j0 = jp * 2;
                float sq0 = fmaxf(xn[i] + an_s[cg1 + j0]     - 2.f * d0, 0.f);
                float sq1 = fmaxf(xn[i] + an_s[cg1 + j0 + 1] - 2.f * d1, 0.f);
                float w0 = fex2(NEG_K * fsqrt_approx(sq0));
                float w1 = fex2(NEG_K * fsqrt_approx(sq1));
                if (n0 + cg1 + j0     >= nEnd) w0 = 0.f;   // tail chunk
                if (n0 + cg1 + j0 + 1 >= nEnd) w1 = 0.f;
                Ws[(cg1 + j0)     * 65 + r0 + i] = w0;
                Ws[(cg1 + j0 + 1) * 65 + r0 + i] = w1;
            }
        }
        __syncthreads();

        // ---------------- GEMM2: acc[r][c] += sum_k W[k][r] * Ms[k][c] ---------
        #pragma unroll 2
        for (int k = 0; k < NT; k++) {
            const float* wrow = Ws + k * 65 + r0;
            unsigned long long w0 = pack2(wrow[0], wrow[0]);
            unsigned long long w1 = pack2(wrow[1], wrow[1]);
            unsigned long long w2 = pack2(wrow[2], wrow[2]);
            unsigned long long w3 = pack2(wrow[3], wrow[3]);
            double2 m0 = *reinterpret_cast<const double2*>(Ms + k * CPAD + cg2);
            double2 m1 = *reinterpret_cast<const double2*>(Ms + k * CPAD + cg2 + 4);
            unsigned long long mA = __double_as_longlong(m0.x);
            unsigned long long mB = __double_as_longlong(m0.y);
            unsigned long long mC = __double_as_longlong(m1.x);
            unsigned long long mD = __double_as_longlong(m1.y);
            fma2(acc[0][0], w0, mA); fma2(acc[0][1], w0, mB);
            fma2(acc[0][2], w0, mC); fma2(acc[0][3], w0, mD);
            fma2(acc[1][0], w1, mA); fma2(acc[1][1], w1, mB);
            fma2(acc[1][2], w1, mC); fma2(acc[1][3], w1, mD);
            fma2(acc[2][0], w2, mA); fma2(acc[2][1], w2, mB);
            fma2(acc[2][2], w2, mC); fma2(acc[2][3], w2, mD);
            fma2(acc[3][0], w3, mA); fma2(acc[3][1], w3, mB);
            fma2(acc[3][2], w3, mC); fma2(acc[3][3], w3, mD);
        }
        __syncthreads();
    }

    // ---- write split partials (cols 0..99 = weighted sums, col 100 = sumexp) ----
    #pragma unroll
    for (int i = 0; i < 4; i++) {
        size_t rowbase = ((size_t)blockIdx.y * CONST_B + (b0 + r0 + i)) * PSTRIDE;
        #pragma unroll
        for (int q = 0; q < 4; q++) {
            float f0, f1;
            unpack2(acc[i][q], f0, f1);
            int c = cg2 + 2 * q;
            if (c     <= CONST_C) g_part[rowbase + c]     = f0;
            if (c + 1 <= CONST_C) g_part[rowbase + c + 1] = f1;
        }
    }
}

// ---------------------------------------------------------------------------
// Kernel 3: deterministic split reduce + normalize.
// ---------------------------------------------------------------------------
__global__ void reduce_kernel(float* __restrict__ out) {
    int i = blockIdx.x * blockDim.x + threadIdx.x;
    if (i >= CONST_B * CONST_C) return;
    int b = i / CONST_C, c = i % CONST_C;
    float num = 0.f, den = 0.f;
    #pragma unroll
    for (int s = 0; s < NSPLIT; s++) {
        const float* p = g_part + ((size_t)s * CONST_B + b) * PSTRIDE;
        num += p[c];
        den += p[CONST_C];
    }
    out[i] = num / den;
}

// ---------------------------------------------------------------------------
extern "C" void kernel_launch(void* const* d_in, const int* in_sizes, int n_in,
                              void* d_out, int out_size)
{
    const float* x = (const float*)d_in[0];   // [2048, 128]
    const float* A = (const float*)d_in[1];   // [100000, 128]
    const float* M = (const float*)d_in[2];   // [100000, 100]
    float* out = (float*)d_out;               // [2048, 100]

    cudaFuncSetAttribute(dsdm_main, cudaFuncAttributeMaxDynamicSharedMemorySize,
                         SMEM_TOTAL);

    anorm_kernel<<<(CONST_N + 7) / 8, 256>>>(A);
    dsdm_main<<<dim3(CONST_B / BM, NSPLIT), THREADS, SMEM_TOTAL>>>(x, A, M);
    reduce_kernel<<<(CONST_B * CONST_C + 255) / 256, 256>>>(out);
}

// round 7
// speedup vs baseline: 11.2229x; 11.2229x over previous
#include <cuda_runtime.h>
#include <cstdint>
#include <cstddef>

// ---------------------------------------------------------------------------
// DSDM classifier via mma.sync bf16 (sm_103-target-safe tensor path):
//   S = x . A^T ; w = exp(-sqrt(|x|^2+|A|^2-2S)/T) ; out = (W.M)/rowsum(W)
// x[2048,128], A[100000,128], M[100000,100], out[2048,100], T=2.
// ---------------------------------------------------------------------------

#define CONST_B   2048
#define CONST_D   128
#define CONST_N   100000
#define CONST_C   100

#define NSPLIT    9
#define NPER      11136               // 87 * 128
#define NPAD      100096              // 782 * 128
#define THREADS   256
#define PSTRIDE   112

// -(1 / (T * ln2)), T = 2
#define NEG_K     (-0.72134752044448169f)

// smem byte offsets
#define SM_XN     0                   // float[128]
#define SM_AN     512                 // 2 bufs x 128 floats
#define SM_X      2048                // 2 halves x 16384 (x tile, bf16 SW128)
#define SM_A      34816               // 2 bufs x (2 halves x 16384)
#define SM_MT     100352              // 2 bufs x (2 halves x 16384)
#define SM_TOTAL  165888

#define SWZ(b)    ((b) ^ (((b) >> 3) & 0x70))

// device scratch (allocation-free)
__device__ float g_anorm[NPAD];
__device__ __align__(256) unsigned short g_Abf[(size_t)CONST_N * CONST_D];
__device__ __align__(256) unsigned short g_Mt[(size_t)128 * NPAD];
__device__ float g_part[(size_t)NSPLIT * CONST_B * PSTRIDE];

// ---------------- asm helpers (all sm_80-baseline features) ----------------
__device__ __forceinline__ uint32_t smem_u32(const void* p) {
    uint32_t a;
    asm("{ .reg .u64 t; cvta.to.shared.u64 t, %1; cvt.u32.u64 %0, t; }"
        : "=r"(a) : "l"(p));
    return a;
}
__device__ __forceinline__ uint32_t bfpack(float lo, float hi) {
    uint32_t r;
    asm("cvt.rn.bf16x2.f32 %0, %1, %2;" : "=r"(r) : "f"(hi), "f"(lo));
    return r;
}
__device__ __forceinline__ float fsqrt_a(float x) {
    float r; asm("sqrt.approx.f32 %0, %1;" : "=f"(r) : "f"(x)); return r;
}
__device__ __forceinline__ float fex2(float x) {
    float r; asm("ex2.approx.f32 %0, %1;" : "=f"(r) : "f"(x)); return r;
}
__device__ __forceinline__ void ldsm4(uint32_t* r, uint32_t addr) {
    asm volatile("ldmatrix.sync.aligned.m8n8.x4.shared.b16 {%0,%1,%2,%3}, [%4];"
                 : "=r"(r[0]), "=r"(r[1]), "=r"(r[2]), "=r"(r[3]) : "r"(addr));
}
__device__ __forceinline__ void mma16816(float* c, const uint32_t* a,
                                         uint32_t b0, uint32_t b1) {
    asm volatile(
        "mma.sync.aligned.m16n8k16.row.col.f32.bf16.bf16.f32 "
        "{%0,%1,%2,%3}, {%4,%5,%6,%7}, {%8,%9}, {%0,%1,%2,%3};"
        : "+f"(c[0]), "+f"(c[1]), "+f"(c[2]), "+f"(c[3])
        : "r"(a[0]), "r"(a[1]), "r"(a[2]), "r"(a[3]), "r"(b0), "r"(b1));
}
__device__ __forceinline__ void cpasync16(uint32_t dst, const void* src) {
    asm volatile("cp.async.cg.shared.global [%0], [%1], 16;"
                 :: "r"(dst), "l"(src) : "memory");
}
#define CP_COMMIT asm volatile("cp.async.commit_group;" ::: "memory")
#define CP_WAIT1  asm volatile("cp.async.wait_group 1;" ::: "memory")
#define CP_WAIT0  asm volatile("cp.async.wait_group 0;" ::: "memory")

// ---------------------------------------------------------------------------
// prep_A: |A_n|^2 (fp32) + A -> bf16 row-major copy. One warp per row.
// ---------------------------------------------------------------------------
__global__ void prep_A(const float* __restrict__ A) {
    int row  = blockIdx.x * 8 + (threadIdx.x >> 5);
    int lane = threadIdx.x & 31;
    if (row >= CONST_N) return;
    float4 v = reinterpret_cast<const float4*>(A + (size_t)row * CONST_D)[lane];
    float s = v.x * v.x + v.y * v.y + v.z * v.z + v.w * v.w;
    #pragma unroll
    for (int o = 16; o; o >>= 1) s += __shfl_xor_sync(0xffffffffu, s, o);
    if (lane == 0) g_anorm[row] = s;
    uint2 p = make_uint2(bfpack(v.x, v.y), bfpack(v.z, v.w));
    reinterpret_cast<uint2*>(g_Abf + (size_t)row * CONST_D)[lane] = p;
}

// ---------------------------------------------------------------------------
// prep_Mt: M[n][c] fp32 -> g_Mt[c][n] bf16, c padded to 128 (row 100 = 1.0),
// n padded to NPAD with zeros. One block per 128-n tile, smem transpose.
// ---------------------------------------------------------------------------
__global__ void prep_Mt(const float* __restrict__ M) {
    extern __shared__ float st[];     // [128][104]
    const int tid = threadIdx.x;
    const int t0  = blockIdx.x * 128;
    for (int idx = tid; idx < 128 * 25; idx += THREADS) {
        int r = idx / 25, q = idx % 25;
        int n = t0 + r;
        float4 v = make_float4(0.f, 0.f, 0.f, 0.f);
        if (n < CONST_N)
            v = reinterpret_cast<const float4*>(M + (size_t)n * CONST_C)[q];
        st[r * 104 + q * 4 + 0] = v.x;
        st[r * 104 + q * 4 + 1] = v.y;
        st[r * 104 + q * 4 + 2] = v.z;
        st[r * 104 + q * 4 + 3] = v.w;
    }
    __syncthreads();
    for (int idx = tid; idx < 128 * 16; idx += THREADS) {
        int c = idx >> 4, nq = idx & 15;
        uint32_t h[4];
        #pragma unroll
        for (int j = 0; j < 4; j++) {
            int nl = nq * 8 + j * 2;
            float f0, f1;
            if (c < CONST_C) {
                f0 = st[nl * 104 + c];
                f1 = st[(nl + 1) * 104 + c];
            } else if (c == CONST_C) {
                f0 = (t0 + nl     < CONST_N) ? 1.f : 0.f;
                f1 = (t0 + nl + 1 < CONST_N) ? 1.f : 0.f;
            } else { f0 = 0.f; f1 = 0.f; }
            h[j] = bfpack(f0, f1);
        }
        reinterpret_cast<uint4*>(g_Mt + (size_t)c * NPAD + t0)[nq] =
            make_uint4(h[0], h[1], h[2], h[3]);
    }
}

// ---------------------------------------------------------------------------
// cp.async staging of one 128-address chunk: A tile + Mt tile + anorms.
// ---------------------------------------------------------------------------
__device__ __forceinline__ void stage_chunk(uint32_t sb, int n0, int nEnd,
                                            int buf, int tid) {
    {   // A chunk: row nl, half hf (k 0-63 / 64-127), SW128
        int nl = tid >> 1, hf = tid & 1;
        int nIdx = n0 + nl; if (nIdx >= nEnd) nIdx = nEnd - 1;
        const char* src = (const char*)(g_Abf + (size_t)nIdx * CONST_D + hf * 64);
        uint32_t dst = sb + SM_A + buf * 32768 + hf * 16384 + (uint32_t)nl * 128;
        uint32_t sw = (uint32_t)(nl & 7) << 4;
        #pragma unroll
        for (int j = 0; j < 8; j++)
            cpasync16(dst + ((uint32_t)(j * 16) ^ sw), src + j * 16);
    }
    {   // Mt chunk: row c (class), half hf (n-local 0-63 / 64-127), SW128
        int c = tid >> 1, hf = tid & 1;
        const char* src = (const char*)(g_Mt + (size_t)c * NPAD + n0 + hf * 64);
        uint32_t dst = sb + SM_MT + buf * 32768 + hf * 16384 + (uint32_t)c * 128;
        uint32_t sw = (uint32_t)(c & 7) << 4;
        #pragma unroll
        for (int j = 0; j < 8; j++)
            cpasync16(dst + ((uint32_t)(j * 16) ^ sw), src + j * 16);
    }
    if (tid < 32)   // g_anorm padded to NPAD -> no OOB
        cpasync16(sb + SM_AN + buf * 512 + tid * 16,
                  (const char*)(g_anorm + n0) + tid * 16);
}

__device__ __forceinline__ float wcalc(float s, float xn, float an,
                                       int nl, int nrem) {
    float q = fmaxf(fmaf(-2.f, s, xn + an), 0.f);
    float w = fex2(NEG_K * fsqrt_a(q));
    return (nl < nrem) ? w : 0.f;
}

// ---------------------------------------------------------------------------
// main fused kernel: grid (16, 9), 256 threads = 8 warps x 16 batch rows.
// ---------------------------------------------------------------------------
__global__ void __launch_bounds__(THREADS, 1)
dsdm_mma(const float* __restrict__ x)
{
    extern __shared__ char smem[];
    const uint32_t sb = smem_u32(smem);
    const int tid  = threadIdx.x;
    const int warp = tid >> 5, lane = tid & 31;
    const int b0   = blockIdx.x * 128;
    const int split = blockIdx.y;
    const int nBeg = split * NPER;
    const int nEnd = (nBeg + NPER < CONST_N) ? nBeg + NPER : CONST_N;
    const int nchunks = (nEnd - nBeg + 127) >> 7;

    float* xn_s = reinterpret_cast<float*>(smem + SM_XN);

    // ---- stage x tile (bf16 SW128 halves) + row norms ----
    for (int r = warp; r < 128; r += 8) {
        float4 v = reinterpret_cast<const float4*>(x + (size_t)(b0 + r) * CONST_D)[lane];
        float sq = v.x * v.x + v.y * v.y + v.z * v.z + v.w * v.w;
        #pragma unroll
        for (int o = 16; o; o >>= 1) sq += __shfl_xor_sync(0xffffffffu, sq, o);
        if (lane == 0) xn_s[r] = sq;
        uint2 p = make_uint2(bfpack(v.x, v.y), bfpack(v.z, v.w));
        uint32_t off = (uint32_t)r * 128 + (lane & 15) * 8;
        *reinterpret_cast<uint2*>(smem + SM_X + (lane >> 4) * 16384 + SWZ(off)) = p;
    }

    // prefetch chunk 0
    stage_chunk(sb, nBeg, nEnd, 0, tid);
    CP_COMMIT;
    __syncthreads();

    // ---- X fragments: A-operand m16k16, loaded once, live all chunks ----
    const int m0 = warp * 16;
    uint32_t xa[8][4];
    {
        int aRow = (lane & 7) + ((lane >> 3) & 1) * 8;   // ldmatrix A-op lane map
        int aKb  = (lane >> 4) * 16;
        uint32_t rb  = sb + SM_X + (uint32_t)(m0 + aRow) * 128;
        uint32_t swr = (uint32_t)(aRow & 7) << 4;
        #pragma unroll
        for (int kk = 0; kk < 8; kk++) {
            uint32_t col = (uint32_t)(((32 * kk) & 127) + aKb) ^ swr;
            ldsm4(xa[kk], rb + (kk >> 2) * 16384 + col);
        }
    }
    const float xnA = xn_s[m0 + (lane >> 2)];
    const float xnB = xn_s[m0 + 8 + (lane >> 2)];

    // B-operand ldmatrix lane map + swizzled column offsets
    const int bRow = (lane & 7) + ((lane >> 4) & 1) * 8;
    const int bKb  = ((lane >> 3) & 1) * 16;
    const uint32_t bsw = (uint32_t)(bRow & 7) << 4;
    uint32_t bcol[8];
    #pragma unroll
    for (int kk = 0; kk < 8; kk++)
        bcol[kk] = (uint32_t)(((32 * kk) & 127) + bKb) ^ bsw;

    const int t4x2 = (lane & 3) * 2;

    float acc[16][4];
    #pragma unroll
    for (int j = 0; j < 16; j++)
        #pragma unroll
        for (int q = 0; q < 4; q++) acc[j][q] = 0.f;

    for (int ch = 0; ch < nchunks; ch++) {
        if (ch + 1 < nchunks) {
            stage_chunk(sb, nBeg + (ch + 1) * 128, nEnd, (ch + 1) & 1, tid);
            CP_COMMIT;
            CP_WAIT1;
        } else {
            CP_WAIT0;
        }
        __syncthreads();

        const int buf  = ch & 1;
        const int nrem = nEnd - (nBeg + ch * 128);
        const uint32_t aTile = sb + SM_A + buf * 32768;
        const uint32_t mTile = sb + SM_MT + buf * 32768;
        const float* an_b = reinterpret_cast<const float*>(smem + SM_AN + buf * 512);

        uint32_t wf[8][4];    // W as GEMM2 A-operand fragments (registers only)

        #pragma unroll
        for (int hn = 0; hn < 2; hn++) {   // n-halves: keeps S regs at 32
            float sacc[8][4];
            #pragma unroll
            for (int j = 0; j < 8; j++)
                #pragma unroll
                for (int q = 0; q < 4; q++) sacc[j][q] = 0.f;

            // GEMM1: S[16 x 64] = X . Achunk^T (k = 128)
            #pragma unroll
            for (int Jp = 0; Jp < 4; Jp++) {
                uint32_t rowb = aTile + (uint32_t)(64 * hn + 16 * Jp + bRow) * 128;
                #pragma unroll
                for (int kk = 0; kk < 8; kk++) {
                    uint32_t b4[4];
                    ldsm4(b4, rowb + (kk >> 2) * 16384 + bcol[kk]);
                    mma16816(sacc[2 * Jp],     xa[kk], b4[0], b4[1]);
                    mma16816(sacc[2 * Jp + 1], xa[kk], b4[2], b4[3]);
                }
            }

            // epilogue: w = exp2(-K*sqrt(xn+an-2S)); S-acc -> W a-frags in regs
            #pragma unroll
            for (int tl = 0; tl < 8; tl++) {
                int nl = 64 * hn + 8 * tl + t4x2;
                float2 anv = *reinterpret_cast<const float2*>(an_b + nl);
                float w0 = wcalc(sacc[tl][0], xnA, anv.x, nl,     nrem);
                float w1 = wcalc(sacc[tl][1], xnA, anv.y, nl + 1, nrem);
                float w2 = wcalc(sacc[tl][2], xnB, anv.x, nl,     nrem);
                float w3 = wcalc(sacc[tl][3], xnB, anv.y, nl + 1, nrem);
                wf[4 * hn + (tl >> 1)][(tl & 1) * 2 + 0] = bfpack(w0, w1);
                wf[4 * hn + (tl >> 1)][(tl & 1) * 2 + 1] = bfpack(w2, w3);
            }
        }

        // GEMM2: ACC[16 x 128] += W . Mt^T (k = n = 128), fp32 accum
        #pragma unroll
        for (int J = 0; J < 8; J++) {
            uint32_t rowb = mTile + (uint32_t)(16 * J + bRow) * 128;
            #pragma unroll
            for (int kk = 0; kk < 8; kk++) {
                uint32_t b4[4];
                ldsm4(b4, rowb + (kk >> 2) * 16384 + bcol[kk]);
                mma16816(acc[2 * J],     wf[kk], b4[0], b4[1]);
                mma16816(acc[2 * J + 1], wf[kk], b4[2], b4[3]);
            }
        }
        __syncthreads();
    }

    // ---- write split partials (cols 0..99 weighted sums, col 100 sumexp) ----
    {
        int rA = b0 + m0 + (lane >> 2);
        size_t baseA = ((size_t)split * CONST_B + rA) * PSTRIDE;
        size_t baseB = baseA + (size_t)8 * PSTRIDE;
        #pragma unroll
        for (int jt = 0; jt < 16; jt++) {
            int c = 8 * jt + t4x2;
            if (c <= CONST_C) {
                g_part[baseA + c] = acc[jt][0];
                g_part[baseB + c] = acc[jt][2];
            }
            if (c + 1 <= CONST_C) {
                g_part[baseA + c + 1] = acc[jt][1];
                g_part[baseB + c + 1] = acc[jt][3];
            }
        }
    }
}

// ---------------------------------------------------------------------------
// reduce: deterministic sum over splits + normalize.
// ---------------------------------------------------------------------------
__global__ void reduce_kernel(float* __restrict__ out) {
    int i = blockIdx.x * blockDim.x + threadIdx.x;
    if (i >= CONST_B * CONST_C) return;
    int b = i / CONST_C, c = i % CONST_C;
    float num = 0.f, den = 0.f;
    #pragma unroll
    for (int s = 0; s < NSPLIT; s++) {
        const float* p = g_part + ((size_t)s * CONST_B + b) * PSTRIDE;
        num += p[c];
        den += p[CONST_C];
    }
    out[i] = num / den;
}

// ---------------------------------------------------------------------------
extern "C" void kernel_launch(void* const* d_in, const int* in_sizes, int n_in,
                              void* d_out, int out_size)
{
    const float* x = (const float*)d_in[0];   // [2048, 128]
    const float* A = (const float*)d_in[1];   // [100000, 128]
    const float* M = (const float*)d_in[2];   // [100000, 100]
    float* out = (float*)d_out;               // [2048, 100]

    cudaFuncSetAttribute(dsdm_mma, cudaFuncAttributeMaxDynamicSharedMemorySize,
                         SM_TOTAL);
    cudaFuncSetAttribute(prep_Mt, cudaFuncAttributeMaxDynamicSharedMemorySize,
                         128 * 104 * 4);

    prep_A<<<CONST_N / 8, 256>>>(A);
    prep_Mt<<<NPAD / 128, THREADS, 128 * 104 * 4>>>(M);
    dsdm_mma<<<dim3(CONST_B / 128, NSPLIT), THREADS, SM_TOTAL>>>(x);
    reduce_kernel<<<(CONST_B * CONST_C + 255) / 256, 256>>>(out);
}